// round 7
// baseline (speedup 1.0000x reference)
#include <cuda_runtime.h>
#include <cuda_fp16.h>
#include <cstdint>

#define TQ    16384
#define DIN   1024
#define DOUT  1024
#define NE    8
#define BM    128
#define BN    128
#define BK    64
#define NKITER (DIN / BK)          // 16
#define MAXTILES (TQ / BM + NE)    // 136
#define NSTAGE 3

// A tile: [128 rows][64 halves + 8 pad]  (m-major, k contiguous)
#define ASTRIDE_H 72
#define ATILE_BYTES (BM * ASTRIDE_H * 2)             // 18432
// B tile: [64 k-rows][128 halves + 8 pad]  (k-major, n contiguous)
#define BSTRIDE_H 136
#define BTILE_BYTES (BK * BSTRIDE_H * 2)             // 17408
#define STAGE_BYTES (ATILE_BYTES + BTILE_BYTES)      // 35840
#define SMEM_BYTES  (NSTAGE * STAGE_BYTES)           // 107520

// ---------------- scratch (device globals; no allocations) ----------------
__device__ int g_offsets[NE + 1];
__device__ int g_cursor[NE];
__device__ int g_perm[TQ];
__device__ int g_tile_expert[MAXTILES];
__device__ int g_tile_start[MAXTILES];
__device__ __half g_xh[(size_t)TQ * DIN];             // x in fp16, PERMUTED (packed by expert)
__device__ __half g_Wh[(size_t)NE * DIN * DOUT];      // W in fp16, SAME layout [e][in][out]

// ---------------- fused init+count+scan (one block) ----------------
__global__ void k_bin(const int* __restrict__ idxs) {
    __shared__ int wh[32][NE];          // per-warp histograms
    const int tid = threadIdx.x;        // 1024 threads
    const int warp = tid >> 5;
    if ((tid & 31) < NE) wh[warp][tid & 31] = 0;
    __syncthreads();
    const int4* iv = reinterpret_cast<const int4*>(idxs);
#pragma unroll
    for (int i = 0; i < 4; i++) {
        int4 v = iv[i * 1024 + tid];
        atomicAdd(&wh[warp][v.x], 1);
        atomicAdd(&wh[warp][v.y], 1);
        atomicAdd(&wh[warp][v.z], 1);
        atomicAdd(&wh[warp][v.w], 1);
    }
    __syncthreads();
    if (tid == 0) {
        int off = 0;
        for (int e = 0; e < NE; e++) {
            int c = 0;
            for (int w = 0; w < 32; w++) c += wh[w][e];
            g_offsets[e] = off;
            g_cursor[e]  = off;
            off += c;
        }
        g_offsets[NE] = off;
        int nt = 0;
        for (int e = 0; e < NE; e++)
            for (int s = g_offsets[e]; s < g_offsets[e + 1]; s += BM) {
                g_tile_expert[nt] = e;
                g_tile_start[nt]  = s;
                nt++;
            }
        for (; nt < MAXTILES; nt++) g_tile_expert[nt] = -1;
    }
}

// ---------------- scatter: build perm (block-aggregated atomics) ----------------
__global__ void k_scatter(const int* __restrict__ idxs) {
    __shared__ int lh[NE];
    __shared__ int base[NE];
    if (threadIdx.x < NE) lh[threadIdx.x] = 0;
    __syncthreads();
    int t = blockIdx.x * blockDim.x + threadIdx.x;
    int e = idxs[t];
    int r = atomicAdd(&lh[e], 1);
    __syncthreads();
    if (threadIdx.x < NE)
        base[threadIdx.x] = atomicAdd(&g_cursor[threadIdx.x], lh[threadIdx.x]);
    __syncthreads();
    g_perm[base[e] + r] = t;
}

// ---------------- prep: gathered x->fp16 pack + W->fp16 convert (no transpose) --------
// blocks [0, TQ):        g_xh[p][:] = half(x[g_perm[p]][:])
// blocks [TQ, TQ+8192):  g_Wh[i] = half(W[i])   (elementwise, 4 per thread)
__global__ void k_prep(const float* __restrict__ x, const float* __restrict__ W) {
    const int tid = threadIdx.x;
    if (blockIdx.x < TQ) {
        int p = blockIdx.x;
        int tok = g_perm[p];
        float4 v = *reinterpret_cast<const float4*>(x + (size_t)tok * DIN + tid * 4);
        __half2 h0 = __float22half2_rn(make_float2(v.x, v.y));
        __half2 h1 = __float22half2_rn(make_float2(v.z, v.w));
        __half* dst = g_xh + (size_t)p * DIN + tid * 4;
        *reinterpret_cast<__half2*>(dst)     = h0;
        *reinterpret_cast<__half2*>(dst + 2) = h1;
    } else {
        size_t i = ((size_t)(blockIdx.x - TQ) * 256 + tid) * 4;
        float4 v = *reinterpret_cast<const float4*>(W + i);
        __half2 h0 = __float22half2_rn(make_float2(v.x, v.y));
        __half2 h1 = __float22half2_rn(make_float2(v.z, v.w));
        *reinterpret_cast<__half2*>(&g_Wh[i])     = h0;
        *reinterpret_cast<__half2*>(&g_Wh[i + 2]) = h1;
    }
}

// ---------------- GEMM helpers ----------------
__device__ __forceinline__ void cp_async16(uint32_t dst, const void* src) {
    asm volatile("cp.async.cg.shared.global [%0], [%1], 16;\n" :: "r"(dst), "l"(src));
}

__device__ __forceinline__ void ldsm_x4(uint32_t r[4], uint32_t addr) {
    asm volatile("ldmatrix.sync.aligned.m8n8.x4.shared.b16 {%0,%1,%2,%3}, [%4];"
                 : "=r"(r[0]), "=r"(r[1]), "=r"(r[2]), "=r"(r[3]) : "r"(addr));
}

__device__ __forceinline__ void ldsm_x4_t(uint32_t r[4], uint32_t addr) {
    asm volatile("ldmatrix.sync.aligned.m8n8.x4.trans.shared.b16 {%0,%1,%2,%3}, [%4];"
                 : "=r"(r[0]), "=r"(r[1]), "=r"(r[2]), "=r"(r[3]) : "r"(addr));
}

__device__ __forceinline__ void mma_f16(float d[4], const uint32_t a[4], const uint32_t b[2]) {
    asm volatile(
        "mma.sync.aligned.m16n8k16.row.col.f32.f16.f16.f32 "
        "{%0,%1,%2,%3}, {%4,%5,%6,%7}, {%8,%9}, {%0,%1,%2,%3};\n"
        : "+f"(d[0]), "+f"(d[1]), "+f"(d[2]), "+f"(d[3])
        : "r"(a[0]), "r"(a[1]), "r"(a[2]), "r"(a[3]),
          "r"(b[0]), "r"(b[1]));
}

__device__ __forceinline__ uint32_t smem_u32(const void* p) {
    return (uint32_t)__cvta_generic_to_shared(p);
}

// ---------------- GEMM (fp16 in, fp32 accum), A pre-packed, B via ldmatrix.trans ------
// grid=(DOUT/BN, MAXTILES): n fastest so CTAs sharing a row-tile hit L2 on packed A rows.
__global__ __launch_bounds__(256, 2)
void k_gemm(const float* __restrict__ bias, float* __restrict__ y)
{
    const int tile = blockIdx.y;
    const int e = g_tile_expert[tile];
    if (e < 0) return;
    const int row0 = g_tile_start[tile];
    const int row_end = g_offsets[e + 1];
    const int n0 = blockIdx.x * BN;

    extern __shared__ __half smem[];
    const uint32_t sbase = smem_u32(smem);

    const int tid  = threadIdx.x;
    const int lane = tid & 31;
    const int warp = tid >> 5;
    const int warpM = warp >> 2;     // 0..1  (64-row slab)
    const int warpN = warp & 3;      // 0..3  (32-col slab)

    const int q  = lane >> 3;        // ldmatrix matrix id
    const int rl = lane & 7;         // row within 8x8 matrix

    // A (non-trans): matrices [m0-7,k0-7][m8-15,k0-7][m0-7,k8-15][m8-15,k8-15]
    uint32_t aoff[4];
#pragma unroll
    for (int mi = 0; mi < 4; mi++) {
        int row = warpM * 64 + mi * 16 + (q & 1) * 8 + rl;
        aoff[mi] = (uint32_t)(row * ASTRIDE_H + (q >> 1) * 8) * 2;
    }
    // B (trans, tile stored [k][n]): matrices [k0-7,nA][k8-15,nA][k0-7,nB][k8-15,nB]
    uint32_t boff[2];
#pragma unroll
    for (int j = 0; j < 2; j++) {
        int krow = (q & 1) * 8 + rl;
        int ncol = warpN * 32 + j * 16 + (q >> 1) * 8;
        boff[j] = ATILE_BYTES + (uint32_t)(krow * BSTRIDE_H + ncol) * 2;
    }

    const __half* wb = g_Wh + (size_t)e * DIN * DOUT + n0;

    int arow[4];
#pragma unroll
    for (int i = 0; i < 4; i++) {
        int r = (i * 256 + tid) >> 3;
        int gr = row0 + r;
        arow[i] = (gr < TQ) ? gr : (TQ - 1);
    }
    const int ccA = tid & 7;          // A chunk col (8 halves)

    auto prefetch = [&](int kt) {
        const uint32_t st = sbase + (kt % NSTAGE) * STAGE_BYTES;
        const int k0 = kt * BK;
#pragma unroll
        for (int i = 0; i < 4; i++) {
            int r = (i * 256 + tid) >> 3;
            cp_async16(st + (uint32_t)(r * ASTRIDE_H + ccA * 8) * 2,
                       g_xh + (size_t)arow[i] * DIN + k0 + ccA * 8);
        }
        // B: 64 k-rows x 128 halves = 16 chunks/row; 256 thr x 4 iters
#pragma unroll
        for (int i = 0; i < 4; i++) {
            int f = i * 256 + tid;
            int kr = f >> 4, nc = f & 15;
            cp_async16(st + ATILE_BYTES + (uint32_t)(kr * BSTRIDE_H + nc * 8) * 2,
                       wb + (size_t)(k0 + kr) * DOUT + nc * 8);
        }
        asm volatile("cp.async.commit_group;\n" ::);
    };

    float acc[4][4][4] = {};   // [mi][nj][frag]

    prefetch(0);
    prefetch(1);

    for (int kt = 0; kt < NKITER; kt++) {
        if (kt < NKITER - 1) {
            asm volatile("cp.async.wait_group 1;\n" ::);
        } else {
            asm volatile("cp.async.wait_group 0;\n" ::);
        }
        __syncthreads();
        if (kt + 2 < NKITER) prefetch(kt + 2);

        const uint32_t st = sbase + (kt % NSTAGE) * STAGE_BYTES;

#pragma unroll
        for (int ks = 0; ks < BK; ks += 16) {
            uint32_t af[4][4], bp[2][4];
#pragma unroll
            for (int mi = 0; mi < 4; mi++)
                ldsm_x4(af[mi], st + aoff[mi] + ks * 2);
#pragma unroll
            for (int j = 0; j < 2; j++)
                ldsm_x4_t(bp[j], st + boff[j] + ks * (BSTRIDE_H * 2));
            // bp[j]: r0,r1 = frag for n-octet 2j; r2,r3 = n-octet 2j+1
#pragma unroll
            for (int mi = 0; mi < 4; mi++)
#pragma unroll
                for (int nj = 0; nj < 4; nj++)
                    mma_f16(acc[mi][nj], af[mi], &bp[nj >> 1][(nj & 1) * 2]);
        }
    }

    // Epilogue: bias + relu + scatter store (perm only here)
    const int grp = lane >> 2;
    const int c4  = lane & 3;
#pragma unroll
    for (int mi = 0; mi < 4; mi++) {
#pragma unroll
        for (int h = 0; h < 2; h++) {
            int mrow = warpM * 64 + mi * 16 + grp + h * 8;
            int gr = row0 + mrow;
            if (gr >= row_end) continue;
            int tok = g_perm[gr];
#pragma unroll
            for (int nj = 0; nj < 4; nj++) {
                int n = n0 + warpN * 32 + nj * 8 + 2 * c4;
                float v0 = acc[mi][nj][h * 2 + 0] + __ldg(&bias[e * DOUT + n]);
                float v1 = acc[mi][nj][h * 2 + 1] + __ldg(&bias[e * DOUT + n + 1]);
                float2 out;
                out.x = fmaxf(v0, 0.0f);
                out.y = fmaxf(v1, 0.0f);
                *reinterpret_cast<float2*>(y + (size_t)tok * DOUT + n) = out;
            }
        }
    }
}

// ---------------- launch ----------------
extern "C" void kernel_launch(void* const* d_in, const int* in_sizes, int n_in,
                              void* d_out, int out_size) {
    const float* x    = (const float*)d_in[0];
    const int*   idxs = (const int*)  d_in[1];
    const float* W    = (const float*)d_in[2];
    const float* b    = (const float*)d_in[3];
    float* y = (float*)d_out;

    cudaFuncSetAttribute(k_gemm, cudaFuncAttributeMaxDynamicSharedMemorySize, SMEM_BYTES);

    k_bin<<<1, 1024>>>(idxs);
    k_scatter<<<TQ / 256, 256>>>(idxs);
    k_prep<<<TQ + NE * DIN * DOUT / 1024, 256>>>(x, W);

    dim3 grid(DOUT / BN, MAXTILES);
    k_gemm<<<grid, 256, SMEM_BYTES>>>(b, y);
}

// round 9
// speedup vs baseline: 1.4235x; 1.4235x over previous
#include <cuda_runtime.h>
#include <cuda_fp16.h>
#include <cstdint>

#define TQ    16384
#define DIN   1024
#define DOUT  1024
#define NE    8
#define BM    128
#define BN    128
#define BK    64
#define NKITER (DIN / BK)          // 16
#define MAXTILES (TQ / BM + NE)    // 136
#define NSTAGE 3

// smem tiles in half: row = 64 halves + 8 pad = 72 halves = 144 B
#define TSTRIDE_H 72
#define TILE_HALVES (BM * TSTRIDE_H)                 // 9216
#define TILE_BYTES  (TILE_HALVES * 2)                // 18432
#define STAGE_BYTES (2 * TILE_BYTES)                 // A + B = 36864
#define SMEM_BYTES  (NSTAGE * STAGE_BYTES)           // 110592

// ---------------- scratch (device globals; no allocations) ----------------
__device__ int g_offsets[NE + 1];
__device__ int g_cursor[NE];
__device__ int g_perm[TQ];
__device__ int g_tile_expert[MAXTILES];
__device__ int g_tile_start[MAXTILES];
__device__ __half g_xh[(size_t)TQ * DIN];             // x in fp16, PERMUTED (packed by expert)
__device__ __half g_Wth[(size_t)NE * DOUT * DIN];     // W^T in fp16: [e][out][in]

// ---------------- fused init+count+scan (one block) ----------------
__global__ void k_bin(const int* __restrict__ idxs) {
    __shared__ int wh[32][NE];          // per-warp histograms
    const int tid = threadIdx.x;        // 1024 threads
    const int warp = tid >> 5;
    if ((tid & 31) < NE) wh[warp][tid & 31] = 0;
    __syncthreads();
    const int4* iv = reinterpret_cast<const int4*>(idxs);
#pragma unroll
    for (int i = 0; i < 4; i++) {
        int4 v = iv[i * 1024 + tid];
        atomicAdd(&wh[warp][v.x], 1);
        atomicAdd(&wh[warp][v.y], 1);
        atomicAdd(&wh[warp][v.z], 1);
        atomicAdd(&wh[warp][v.w], 1);
    }
    __syncthreads();
    if (tid == 0) {
        int off = 0;
        for (int e = 0; e < NE; e++) {
            int c = 0;
            for (int w = 0; w < 32; w++) c += wh[w][e];
            g_offsets[e] = off;
            g_cursor[e]  = off;
            off += c;
        }
        g_offsets[NE] = off;
        int nt = 0;
        for (int e = 0; e < NE; e++)
            for (int s = g_offsets[e]; s < g_offsets[e + 1]; s += BM) {
                g_tile_expert[nt] = e;
                g_tile_start[nt]  = s;
                nt++;
            }
        for (; nt < MAXTILES; nt++) g_tile_expert[nt] = -1;
    }
}

// ---------------- scatter: build perm (block-aggregated atomics) ----------------
__global__ void k_scatter(const int* __restrict__ idxs) {
    __shared__ int lh[NE];
    __shared__ int base[NE];
    if (threadIdx.x < NE) lh[threadIdx.x] = 0;
    __syncthreads();
    int t = blockIdx.x * blockDim.x + threadIdx.x;
    int e = idxs[t];
    int r = atomicAdd(&lh[e], 1);
    __syncthreads();
    if (threadIdx.x < NE)
        base[threadIdx.x] = atomicAdd(&g_cursor[threadIdx.x], lh[threadIdx.x]);
    __syncthreads();
    g_perm[base[e] + r] = t;
}

// ---------------- prep: gathered x->fp16 pack  +  W transpose->fp16 ----------------
// blocks [0, TQ):            g_xh[p][:] = half(x[g_perm[p]][:])
// blocks [TQ, TQ + 8*1024):  g_Wth[e][o][k] = half(W[e][k][o])
__global__ void k_prep(const float* __restrict__ x, const float* __restrict__ W) {
    const int tid = threadIdx.x;
    if (blockIdx.x < TQ) {
        int p = blockIdx.x;
        int tok = g_perm[p];
        float4 v = *reinterpret_cast<const float4*>(x + (size_t)tok * DIN + tid * 4);
        __half2 h0 = __float22half2_rn(make_float2(v.x, v.y));
        __half2 h1 = __float22half2_rn(make_float2(v.z, v.w));
        __half* dst = g_xh + (size_t)p * DIN + tid * 4;
        *reinterpret_cast<__half2*>(dst)     = h0;
        *reinterpret_cast<__half2*>(dst + 2) = h1;
    } else {
        __shared__ float t[32][33];
        int bid = blockIdx.x - TQ;
        int e = bid >> 10;
        int rem = bid & 1023;
        int k0 = (rem >> 5) * 32, o0 = (rem & 31) * 32;
        const float* Ws = W + (size_t)e * DIN * DOUT;
        __half* Wd = g_Wth + (size_t)e * DOUT * DIN;
        int tx = tid & 31, ty = tid >> 5;   // 32 x 8
#pragma unroll
        for (int j = 0; j < 4; j++)
            t[ty + j * 8][tx] = Ws[(size_t)(k0 + ty + j * 8) * DOUT + o0 + tx];
        __syncthreads();
#pragma unroll
        for (int j = 0; j < 4; j++)
            Wd[(size_t)(o0 + ty + j * 8) * DIN + k0 + tx] = __float2half(t[tx][ty + j * 8]);
    }
}

// ---------------- GEMM helpers ----------------
__device__ __forceinline__ void cp_async16(uint32_t dst, const void* src) {
    asm volatile("cp.async.cg.shared.global [%0], [%1], 16;\n" :: "r"(dst), "l"(src));
}

__device__ __forceinline__ void ldsm_x4(uint32_t r[4], uint32_t addr) {
    asm volatile("ldmatrix.sync.aligned.m8n8.x4.shared.b16 {%0,%1,%2,%3}, [%4];"
                 : "=r"(r[0]), "=r"(r[1]), "=r"(r[2]), "=r"(r[3]) : "r"(addr));
}

__device__ __forceinline__ void mma_f16(float d[4], const uint32_t a[4], const uint32_t b[2]) {
    asm volatile(
        "mma.sync.aligned.m16n8k16.row.col.f32.f16.f16.f32 "
        "{%0,%1,%2,%3}, {%4,%5,%6,%7}, {%8,%9}, {%0,%1,%2,%3};\n"
        : "+f"(d[0]), "+f"(d[1]), "+f"(d[2]), "+f"(d[3])
        : "r"(a[0]), "r"(a[1]), "r"(a[2]), "r"(a[3]),
          "r"(b[0]), "r"(b[1]));
}

__device__ __forceinline__ uint32_t smem_u32(const void* p) {
    return (uint32_t)__cvta_generic_to_shared(p);
}

// ---------------- GEMM (fp16 inputs, fp32 accum), A pre-packed, B n-major --------------
// grid=(DOUT/BN, MAXTILES): n fastest so CTAs sharing a row-tile hit L2 on packed A rows.
__global__ __launch_bounds__(256, 2)
void k_gemm(const float* __restrict__ bias, float* __restrict__ y)
{
    const int tile = blockIdx.y;
    const int e = g_tile_expert[tile];
    if (e < 0) return;
    const int row0 = g_tile_start[tile];
    const int row_end = g_offsets[e + 1];
    const int n0 = blockIdx.x * BN;

    extern __shared__ __half smem[];
    const uint32_t sbase = smem_u32(smem);

    const int tid  = threadIdx.x;
    const int lane = tid & 31;
    const int warp = tid >> 5;
    const int warpM = warp >> 2;     // 0..1  (64-row slab)
    const int warpN = warp & 3;      // 0..3  (32-col slab)

    const int q  = lane >> 3;        // ldmatrix matrix id
    const int rl = lane & 7;         // row within 8x8 matrix

    // A: matrices [m0-7,k0-7][m8-15,k0-7][m0-7,k8-15][m8-15,k8-15]
    uint32_t aoff[4];
#pragma unroll
    for (int mi = 0; mi < 4; mi++) {
        int row = warpM * 64 + mi * 16 + (q & 1) * 8 + rl;
        aoff[mi] = (uint32_t)(row * TSTRIDE_H + (q >> 1) * 8) * 2;
    }
    // B (n-major rows of W^T): matrices [n0-7,k0-7][n0-7,k8-15][n8-15,k0-7][n8-15,k8-15]
    uint32_t boff[2];
#pragma unroll
    for (int j = 0; j < 2; j++) {
        int row = warpN * 32 + 16 * j + (q >> 1) * 8 + rl;
        boff[j] = (uint32_t)(row * TSTRIDE_H + (q & 1) * 8) * 2 + TILE_BYTES;
    }

    const __half* wt = g_Wth + (size_t)(e * DOUT + n0) * DIN;
    const int cc = tid & 7;           // 16B chunk col (8 halves each)

    int arow[4];
#pragma unroll
    for (int i = 0; i < 4; i++) {
        int r = (i * 256 + tid) >> 3;
        int gr = row0 + r;
        arow[i] = (gr < TQ) ? gr : (TQ - 1);
    }

    auto prefetch = [&](int kt) {
        const uint32_t st = sbase + (kt % NSTAGE) * STAGE_BYTES;
        const int k0 = kt * BK;
#pragma unroll
        for (int i = 0; i < 4; i++) {
            int r = (i * 256 + tid) >> 3;
            cp_async16(st + (uint32_t)(r * TSTRIDE_H + cc * 8) * 2,
                       g_xh + (size_t)arow[i] * DIN + k0 + cc * 8);
        }
#pragma unroll
        for (int i = 0; i < 4; i++) {
            int n = (i * 256 + tid) >> 3;
            cp_async16(st + TILE_BYTES + (uint32_t)(n * TSTRIDE_H + cc * 8) * 2,
                       wt + (size_t)n * DIN + k0 + cc * 8);
        }
        asm volatile("cp.async.commit_group;\n" ::);
    };

    float acc[4][4][4] = {};   // [mi][nj][frag]

    prefetch(0);
    prefetch(1);

    for (int kt = 0; kt < NKITER; kt++) {
        if (kt < NKITER - 1) {
            asm volatile("cp.async.wait_group 1;\n" ::);
        } else {
            asm volatile("cp.async.wait_group 0;\n" ::);
        }
        __syncthreads();
        if (kt + 2 < NKITER) prefetch(kt + 2);

        const uint32_t st = sbase + (kt % NSTAGE) * STAGE_BYTES;

#pragma unroll
        for (int ks = 0; ks < BK; ks += 16) {
            uint32_t af[4][4], bp[2][4];
#pragma unroll
            for (int mi = 0; mi < 4; mi++)
                ldsm_x4(af[mi], st + aoff[mi] + ks * 2);
#pragma unroll
            for (int j = 0; j < 2; j++)
                ldsm_x4(bp[j], st + boff[j] + ks * 2);
            // bp[j]: r0,r1 = B frag for n-octet 2j; r2,r3 = n-octet 2j+1
#pragma unroll
            for (int mi = 0; mi < 4; mi++)
#pragma unroll
                for (int nj = 0; nj < 4; nj++)
                    mma_f16(acc[mi][nj], af[mi], &bp[nj >> 1][(nj & 1) * 2]);
        }
    }

    // Epilogue: bias + relu + scatter store (perm only here)
    const int grp = lane >> 2;
    const int c4  = lane & 3;
#pragma unroll
    for (int mi = 0; mi < 4; mi++) {
#pragma unroll
        for (int h = 0; h < 2; h++) {
            int mrow = warpM * 64 + mi * 16 + grp + h * 8;
            int gr = row0 + mrow;
            if (gr >= row_end) continue;
            int tok = g_perm[gr];
#pragma unroll
            for (int nj = 0; nj < 4; nj++) {
                int n = n0 + warpN * 32 + nj * 8 + 2 * c4;
                float v0 = acc[mi][nj][h * 2 + 0] + __ldg(&bias[e * DOUT + n]);
                float v1 = acc[mi][nj][h * 2 + 1] + __ldg(&bias[e * DOUT + n + 1]);
                float2 out;
                out.x = fmaxf(v0, 0.0f);
                out.y = fmaxf(v1, 0.0f);
                *reinterpret_cast<float2*>(y + (size_t)tok * DOUT + n) = out;
            }
        }
    }
}

// ---------------- launch ----------------
extern "C" void kernel_launch(void* const* d_in, const int* in_sizes, int n_in,
                              void* d_out, int out_size) {
    const float* x    = (const float*)d_in[0];
    const int*   idxs = (const int*)  d_in[1];
    const float* W    = (const float*)d_in[2];
    const float* b    = (const float*)d_in[3];
    float* y = (float*)d_out;

    cudaFuncSetAttribute(k_gemm, cudaFuncAttributeMaxDynamicSharedMemorySize, SMEM_BYTES);

    k_bin<<<1, 1024>>>(idxs);
    k_scatter<<<TQ / 256, 256>>>(idxs);
    k_prep<<<TQ + NE * (DIN / 32) * (DOUT / 32), 256>>>(x, W);

    dim3 grid(DOUT / BN, MAXTILES);
    k_gemm<<<grid, 256, SMEM_BYTES>>>(b, y);
}